// round 4
// baseline (speedup 1.0000x reference)
#include <cuda_runtime.h>
#include <cstdint>

// Problem constants (fixed shapes for this problem)
#define B_TOTAL   65536
#define C_CLS     2
#define P_DIM     41
#define L_DIM     4
#define PL        (P_DIM * L_DIM)          // 164
#define CPL       (C_CLS * PL)             // 328
#define BPB       32                        // batches per block
#define THREADS   256
#define NBLOCKS   (B_TOTAL / BPB)           // 2048
#define SL        332                       // padded logits row stride (floats), conflict-free
#define ST        168                       // padded target row stride (bytes), conflict-free

__device__ float g_partials[NBLOCKS];

__global__ __launch_bounds__(THREADS)
void lace_main_kernel(const float* __restrict__ logits,
                      const int* __restrict__ targets)
{
    __shared__ float slog[BPB * SL];                 // 42496 B
    __shared__ unsigned char stgt[BPB * ST];         // 5376 B
    __shared__ float warpsums[4];

    const int tid = threadIdx.x;
    const int blk = blockIdx.x;

    // ---- Stage logits: 32 batches * 328 floats = 2624 float4, fully coalesced ----
    {
        const float4* gL = (const float4*)(logits + (size_t)blk * (BPB * CPL));
        #pragma unroll
        for (int it = 0; it < 2624 / THREADS + 1; ++it) {
            int i = tid + it * THREADS;
            if (i < 2624) {
                float4 v = gL[i];
                int b  = i / 82;             // 82 float4 per batch (328/4)
                int r4 = i - b * 82;
                *(float4*)&slog[b * SL + r4 * 4] = v;
            }
        }
    }

    // ---- Stage targets (int32): 32 batches * 164 int = 1312 int4, coalesced ----
    {
        const int4* gT = (const int4*)(targets + (size_t)blk * (BPB * PL));
        #pragma unroll
        for (int it = 0; it < 1312 / THREADS + 1; ++it) {
            int i = tid + it * THREADS;
            if (i < 1312) {
                int4 v = gT[i];
                int b = i / 41;              // 41 int4 per batch (164/4)
                int r = (i - b * 41) * 4;
                unsigned char* d = &stgt[b * ST + r];
                d[0] = (unsigned char)v.x;
                d[1] = (unsigned char)v.y;
                d[2] = (unsigned char)v.z;
                d[3] = (unsigned char)v.w;
            }
        }
    }

    __syncthreads();

    // ---- Compute: 128 strip-threads, one (b, l) strip each, loop over P ----
    float sum = 0.0f;
    if (tid < BPB * L_DIM) {
        const int b = tid >> 2;
        const int l = tid & 3;
        const float* pL = &slog[b * SL + l];           // class 0 at +0, class 1 at +164
        const unsigned char* pT = &stgt[b * ST + l];

        int tm2 = 0, tm1 = 0;
        int t0  = pT[0];
        int tp1 = pT[4];
        int tp2 = pT[8];
        bool predPrev = false;

        #pragma unroll
        for (int p = 0; p < P_DIM; ++p) {
            float l0 = pL[p * 4];
            float l1 = pL[PL + p * 4];

            // cross-entropy with C=2: loss = softplus(l_other - l_target)
            float lt = t0 ? l1 : l0;
            float lo = t0 ? l0 : l1;
            float d  = lo - lt;
            float z  = fmaxf(d, 0.0f);
            float loss = z + __logf(1.0f + __expf(d - z - z));

            // boundary weight (targets are 0/1 -> |a-b| == a^b)
            float w = 1.0f;
            if (p > 0)          w += (float)(t0 ^ tm1);
            if (p < P_DIM - 1)  w += (float)(tp1 ^ t0);
            if (p > 1)          w += 0.5f * (float)(t0 ^ tm2);
            if (p < P_DIM - 2)  w += 0.5f * (float)(tp2 ^ t0);

            float tot = loss * w;

            // connectivity: argmax ties -> index 0, so pred = (l1 > l0)
            bool pred = l1 > l0;
            if (p > 0 && pred != predPrev) tot += 0.001f;
            predPrev = pred;

            sum += tot;

            // advance rolling target window
            tm2 = tm1; tm1 = t0; t0 = tp1; tp1 = tp2;
            tp2 = (p + 3 < P_DIM) ? pT[(p + 3) * 4] : 0;
        }

        // warp reduce (4 active warps)
        #pragma unroll
        for (int o = 16; o > 0; o >>= 1)
            sum += __shfl_down_sync(0xffffffffu, sum, o);
        if ((tid & 31) == 0) warpsums[tid >> 5] = sum;
    }
    __syncthreads();

    if (tid == 0)
        g_partials[blk] = warpsums[0] + warpsums[1] + warpsums[2] + warpsums[3];
}

__global__ __launch_bounds__(1024)
void lace_reduce_kernel(float* __restrict__ out)
{
    __shared__ float s[1024];
    const int t = threadIdx.x;
    s[t] = g_partials[t] + g_partials[t + 1024];
    __syncthreads();
    #pragma unroll
    for (int o = 512; o > 0; o >>= 1) {
        if (t < o) s[t] += s[t + o];
        __syncthreads();
    }
    if (t == 0)
        out[0] = s[0] * (1.0f / ((float)B_TOTAL * (float)P_DIM * (float)L_DIM));
}

extern "C" void kernel_launch(void* const* d_in, const int* in_sizes, int n_in,
                              void* d_out, int out_size)
{
    const float* logits  = (const float*)d_in[0];
    const int*   targets = (const int*)d_in[1];
    float*       out     = (float*)d_out;

    lace_main_kernel<<<NBLOCKS, THREADS>>>(logits, targets);
    lace_reduce_kernel<<<1, 1024>>>(out);
}

// round 5
// speedup vs baseline: 1.0801x; 1.0801x over previous
#include <cuda_runtime.h>
#include <cstdint>

// Problem constants (fixed shapes for this problem)
#define B_TOTAL   65536
#define C_CLS     2
#define P_DIM     41
#define L_DIM     4
#define PL        (P_DIM * L_DIM)          // 164
#define CPL       (C_CLS * PL)             // 328
#define BPB       32                        // batches per block
#define THREADS   256
#define NBLOCKS   (B_TOTAL / BPB)           // 2048
#define SL        332                       // padded logits row stride (floats), conflict-free
#define ST        168                       // padded target row stride (bytes), conflict-free

__device__ float        g_partials[NBLOCKS];
__device__ unsigned int g_count = 0;         // ticket counter; returns to 0 every launch

__global__ __launch_bounds__(THREADS)
void lace_fused_kernel(const float* __restrict__ logits,
                       const int* __restrict__ targets,
                       float* __restrict__ out)
{
    __shared__ float slog[BPB * SL];                 // 42496 B
    __shared__ unsigned char stgt[BPB * ST];         // 5376 B
    __shared__ float warpsums[8];
    __shared__ float redsums[8];
    __shared__ bool  isLast;

    const int tid = threadIdx.x;
    const int blk = blockIdx.x;

    // ---- Stage logits: 32 batches * 328 floats = 2624 float4, fully coalesced ----
    {
        const float4* gL = (const float4*)(logits + (size_t)blk * (BPB * CPL));
        #pragma unroll
        for (int it = 0; it < 11; ++it) {
            int i = tid + it * THREADS;
            if (i < 2624) {
                float4 v = gL[i];
                int b  = i / 82;             // 82 float4 per batch (328/4)
                int r4 = i - b * 82;
                *(float4*)&slog[b * SL + r4 * 4] = v;
            }
        }
    }

    // ---- Stage targets (int32): 32 batches * 164 int = 1312 int4, coalesced ----
    {
        const int4* gT = (const int4*)(targets + (size_t)blk * (BPB * PL));
        #pragma unroll
        for (int it = 0; it < 6; ++it) {
            int i = tid + it * THREADS;
            if (i < 1312) {
                int4 v = gT[i];
                int b = i / 41;              // 41 int4 per batch (164/4)
                int r = (i - b * 41) * 4;
                unsigned char* d = &stgt[b * ST + r];
                d[0] = (unsigned char)v.x;
                d[1] = (unsigned char)v.y;
                d[2] = (unsigned char)v.z;
                d[3] = (unsigned char)v.w;
            }
        }
    }

    __syncthreads();

    // ---- Compute: 256 threads, each handles one (b, l) strip HALF over P ----
    // threads 0..127: half 0 (p = 0..20), threads 128..255: half 1 (p = 21..40)
    float sum = 0.0f;
    {
        const int half = tid >> 7;                     // 0 or 1
        const int st   = tid & 127;
        const int b = st >> 2;
        const int l = st & 3;
        const float* pL = &slog[b * SL + l];           // class 0 at +0, class 1 at +164
        const unsigned char* pT = &stgt[b * ST + l];

        const int ph = half ? 21 : 0;                  // first p of this half
        const int np = half ? 20 : 21;                 // iterations in this half

        // rolling target window initialized at p = ph (halo reads from smem)
        int tm2 = (ph > 1) ? pT[(ph - 2) * 4] : 0;
        int tm1 = (ph > 0) ? pT[(ph - 1) * 4] : 0;
        int t0  = pT[ph * 4];
        int tp1 = pT[(ph + 1) * 4];
        int tp2 = pT[(ph + 2) * 4];
        bool predPrev = half ? (pL[PL + 20 * 4] > pL[20 * 4]) : false;

        #pragma unroll
        for (int i = 0; i < 21; ++i) {
            if (i >= np) break;
            const int p = ph + i;
            float l0 = pL[p * 4];
            float l1 = pL[PL + p * 4];

            // cross-entropy with C=2: loss = softplus(l_other - l_target)
            float lt = t0 ? l1 : l0;
            float lo = t0 ? l0 : l1;
            float d  = lo - lt;
            float z  = fmaxf(d, 0.0f);
            float loss = z + __logf(1.0f + __expf(d - z - z));

            // boundary weight (targets are 0/1 -> |a-b| == a^b)
            float w = 1.0f;
            if (p > 0)          w += (float)(t0 ^ tm1);
            if (p < P_DIM - 1)  w += (float)(tp1 ^ t0);
            if (p > 1)          w += 0.5f * (float)(t0 ^ tm2);
            if (p < P_DIM - 2)  w += 0.5f * (float)(tp2 ^ t0);

            float tot = loss * w;

            // connectivity: argmax ties -> index 0, so pred = (l1 > l0)
            bool pred = l1 > l0;
            if (p > 0 && pred != predPrev) tot += 0.001f;
            predPrev = pred;

            sum += tot;

            // advance rolling target window
            tm2 = tm1; tm1 = t0; t0 = tp1; tp1 = tp2;
            tp2 = (p + 3 < P_DIM) ? pT[(p + 3) * 4] : 0;
        }

        // warp reduce (8 warps)
        #pragma unroll
        for (int o = 16; o > 0; o >>= 1)
            sum += __shfl_down_sync(0xffffffffu, sum, o);
        if ((tid & 31) == 0) warpsums[tid >> 5] = sum;
    }
    __syncthreads();

    // ---- Per-block partial + last-block fused reduction ----
    if (tid == 0) {
        float bs = 0.0f;
        #pragma unroll
        for (int i = 0; i < 8; ++i) bs += warpsums[i];
        g_partials[blk] = bs;
        __threadfence();
        unsigned int old = atomicAdd(&g_count, 1u);
        isLast = (old == NBLOCKS - 1);
    }
    __syncthreads();

    if (isLast) {
        // fixed-order deterministic reduction of 2048 partials by 256 threads
        float s = 0.0f;
        #pragma unroll
        for (int it = 0; it < NBLOCKS / THREADS; ++it)
            s += g_partials[tid + it * THREADS];
        #pragma unroll
        for (int o = 16; o > 0; o >>= 1)
            s += __shfl_down_sync(0xffffffffu, s, o);
        if ((tid & 31) == 0) redsums[tid >> 5] = s;
        __syncthreads();
        if (tid == 0) {
            float t = 0.0f;
            #pragma unroll
            for (int i = 0; i < 8; ++i) t += redsums[i];
            out[0] = t * (1.0f / ((float)B_TOTAL * (float)P_DIM * (float)L_DIM));
            g_count = 0;                 // reset for next graph replay
        }
    }
}

extern "C" void kernel_launch(void* const* d_in, const int* in_sizes, int n_in,
                              void* d_out, int out_size)
{
    const float* logits  = (const float*)d_in[0];
    const int*   targets = (const int*)d_in[1];
    float*       out     = (float*)d_out;

    lace_fused_kernel<<<NBLOCKS, THREADS>>>(logits, targets, out);
}